// round 7
// baseline (speedup 1.0000x reference)
#include <cuda_runtime.h>
#include <cuda_bf16.h>

#define NSTEP 365
#define NGRID 50000
#define PRECS_F 1e-5f
#define PF 10          // prefetch depth (register ring)
#define BLK 352        // 11 warps; ceil(50000/352)=143 blocks <= 148 SMs -> 1 block/SM, balanced

__global__ __launch_bounds__(BLK, 1)
void hbv_kernel(const float* __restrict__ x,
                const float* __restrict__ params,
                float* __restrict__ out)
{
    const int g = blockIdx.x * BLK + threadIdx.x;
    if (g >= NGRID) return;

    // ---- load & scale the 12 parameters ----
    const float* pp = params + (size_t)g * 14;
    float raw[12];
#pragma unroll
    for (int i = 0; i < 12; i++) raw[i] = pp[i];

    const float BETA  = 1.0f   + raw[0]  * 5.0f;
    const float FC    = 50.0f  + raw[1]  * 950.0f;
    const float K0    = 0.05f  + raw[2]  * 0.85f;
    const float K1    = 0.01f  + raw[3]  * 0.49f;
    const float K2    = 0.001f + raw[4]  * 0.199f;
    const float LP    = 0.2f   + raw[5]  * 0.8f;
    const float PERCp =          raw[6]  * 10.0f;
    const float UZL   =          raw[7]  * 100.0f;
    const float TT    = -2.5f  + raw[8]  * 5.0f;
    const float CFMAX = 0.5f   + raw[9]  * 9.5f;
    const float CFR   =          raw[10] * 0.1f;
    const float CWH   =          raw[11] * 0.2f;

    const float CFRC    = CFR * CFMAX;
    const float invFC   = 1.0f / FC;
    const float invLPFC = 1.0f / (LP * FC);

    // ---- state ----
    float SNOWPACK = 1e-3f, MELTWATER = 1e-3f, SM = 1e-3f, SUZ = 1e-3f, SLZ = 1e-3f;

    const float* xp = x + (size_t)g * 3;
    const size_t  tstride = (size_t)NGRID * 3;
    float* op = out + g;

    // ---- depth-PF register prefetch ring ----
    float bP[PF], bT[PF], bE[PF];
#pragma unroll
    for (int i = 0; i < PF; i++) {
        const float* q = xp + (size_t)i * tstride;
        bP[i] = __ldcs(q);
        bT[i] = __ldcs(q + 1);
        bE[i] = __ldcs(q + 2);
    }

    int t0 = 0;

    // ======== main loop: prefetch always in-range (t0 + 2*PF <= NSTEP) ========
#pragma unroll 1
    for (; t0 + 2 * PF <= NSTEP; t0 += PF) {
#pragma unroll
        for (int i = 0; i < PF; i++) {
            const int t = t0 + i;

            const float P = bP[i];
            const float T = bT[i];
            const float E = bE[i];

            // unguarded prefetch of step t+PF
            {
                const float* q = xp + (size_t)(t + PF) * tstride;
                bP[i] = __ldcs(q);
                bT[i] = __ldcs(q + 1);
                bE[i] = __ldcs(q + 2);
            }

            // ---- snow routine ----
            const bool  rain = (T >= TT);
            const float RAIN = rain ? P : 0.0f;
            const float SNOW = rain ? 0.0f : P;
            SNOWPACK += SNOW;

            const float melt = fminf(fmaxf(CFMAX * (T - TT), 0.0f), SNOWPACK);
            MELTWATER += melt;
            SNOWPACK  -= melt;

            const float refr = fminf(fmaxf(CFRC * (TT - T), 0.0f), MELTWATER);
            SNOWPACK  += refr;
            MELTWATER -= refr;

            const float tosoil = fmaxf(MELTWATER - CWH * SNOWPACK, 0.0f);
            MELTWATER -= tosoil;

            // ---- soil routine ----
            const float r  = SM * invFC;
            const float sw = __saturatef(__powf(r, BETA));

            const float rt       = RAIN + tosoil;
            const float recharge = rt * sw;
            SM += rt - recharge;

            const float excess = fmaxf(SM - FC, 0.0f);
            SM -= excess;

            const float evapf = __saturatef(SM * invLPFC);
            const float ETact = fminf(SM, E * evapf);
            SM = fmaxf(SM - ETact, PRECS_F);

            // ---- response routine ----
            SUZ += recharge + excess;
            const float PERC = fminf(SUZ, PERCp);
            SUZ -= PERC;
            const float Q0 = K0 * fmaxf(SUZ - UZL, 0.0f);
            SUZ -= Q0;
            const float Q1 = K1 * SUZ;
            SUZ -= Q1;
            SLZ += PERC;
            const float Q2 = K2 * SLZ;
            SLZ -= Q2;

            __stcs(op + (size_t)t * NGRID, Q0 + Q1 + Q2);
        }
    }

    // ======== guarded tail (last <= 2*PF steps) ========
#pragma unroll 1
    for (; t0 < NSTEP; t0 += PF) {
#pragma unroll
        for (int i = 0; i < PF; i++) {
            const int t = t0 + i;
            if (t >= NSTEP) break;

            const float P = bP[i];
            const float T = bT[i];
            const float E = bE[i];

            const int tn = t + PF;
            if (tn < NSTEP) {
                const float* q = xp + (size_t)tn * tstride;
                bP[i] = __ldcs(q);
                bT[i] = __ldcs(q + 1);
                bE[i] = __ldcs(q + 2);
            }

            const bool  rain = (T >= TT);
            const float RAIN = rain ? P : 0.0f;
            const float SNOW = rain ? 0.0f : P;
            SNOWPACK += SNOW;

            const float melt = fminf(fmaxf(CFMAX * (T - TT), 0.0f), SNOWPACK);
            MELTWATER += melt;
            SNOWPACK  -= melt;

            const float refr = fminf(fmaxf(CFRC * (TT - T), 0.0f), MELTWATER);
            SNOWPACK  += refr;
            MELTWATER -= refr;

            const float tosoil = fmaxf(MELTWATER - CWH * SNOWPACK, 0.0f);
            MELTWATER -= tosoil;

            const float r  = SM * invFC;
            const float sw = __saturatef(__powf(r, BETA));

            const float rt       = RAIN + tosoil;
            const float recharge = rt * sw;
            SM += rt - recharge;

            const float excess = fmaxf(SM - FC, 0.0f);
            SM -= excess;

            const float evapf = __saturatef(SM * invLPFC);
            const float ETact = fminf(SM, E * evapf);
            SM = fmaxf(SM - ETact, PRECS_F);

            SUZ += recharge + excess;
            const float PERC = fminf(SUZ, PERCp);
            SUZ -= PERC;
            const float Q0 = K0 * fmaxf(SUZ - UZL, 0.0f);
            SUZ -= Q0;
            const float Q1 = K1 * SUZ;
            SUZ -= Q1;
            SLZ += PERC;
            const float Q2 = K2 * SLZ;
            SLZ -= Q2;

            __stcs(op + (size_t)t * NGRID, Q0 + Q1 + Q2);
        }
    }
}

extern "C" void kernel_launch(void* const* d_in, const int* in_sizes, int n_in,
                              void* d_out, int out_size)
{
    const float* x      = (const float*)d_in[0];   // (365, 50000, 3)
    const float* params = (const float*)d_in[1];   // (50000, 14)
    float* out = (float*)d_out;                    // (365, 50000, 1)

    const int blocks = (NGRID + BLK - 1) / BLK;    // 143
    hbv_kernel<<<blocks, BLK>>>(x, params, out);
}

// round 9
// speedup vs baseline: 1.5393x; 1.5393x over previous
#include <cuda_runtime.h>
#include <cuda_bf16.h>
#include <cstdint>

#define NSTEP   365
#define NGRID   50000
#define PRECS_F 1e-5f
#define BLK     352                     // 11 warps; 143 blocks -> 1 block/SM, balanced
#define CHUNK   16                      // timesteps staged per smem buffer
#define ROWB    (BLK * 12)              // 4224 bytes of x per timestep per block
#define BUFB    (ROWB * CHUNK)          // 67584 bytes per buffer
#define NCH     ((NSTEP + CHUNK - 1) / CHUNK)   // 23 chunks (22 full + 13-step tail)

extern __shared__ char smem_raw[];      // 2 * BUFB (double buffer)

// Stage `nrows` timestep-rows of this block's x slice into sbuf via cp.async.
// Every thread executes the commit (uniform), so group counting stays aligned.
__device__ __forceinline__ void stage_chunk(const char* __restrict__ xbase,
                                            char* sbuf, int t0, int nrows,
                                            int g0, int perrow, int tid)
{
    if (tid < perrow) {
        const char* gsrc = xbase + (size_t)t0 * (size_t)(NGRID * 12)
                                 + (size_t)g0 * 12 + (size_t)tid * 16;
        uint32_t sdst = (uint32_t)__cvta_generic_to_shared(sbuf) + tid * 16;
#pragma unroll
        for (int r = 0; r < CHUNK; r++) {
            if (r < nrows) {
                asm volatile("cp.async.cg.shared.global [%0], [%1], 16;\n"
                             :: "r"(sdst + r * ROWB),
                                "l"(gsrc + (size_t)r * (size_t)(NGRID * 12))
                             : "memory");
            }
        }
    }
    asm volatile("cp.async.commit_group;\n" ::: "memory");
}

__global__ __launch_bounds__(BLK, 1)
void hbv_kernel(const float* __restrict__ x,
                const float* __restrict__ params,
                float* __restrict__ out)
{
    const int tid = threadIdx.x;
    const int g0  = blockIdx.x * BLK;
    const int g   = g0 + tid;
    const bool active = (g < NGRID);

    const int ncells = min(BLK, NGRID - g0);       // 352, or 16 for last block
    const int perrow = (ncells * 12) / 16;         // 16B cp.async ops per row

    char* buf0 = smem_raw;
    char* buf1 = smem_raw + BUFB;

    // ---- kick off the first two chunk loads immediately ----
    const char* xb = (const char*)x;
    stage_chunk(xb, buf0, 0,     CHUNK, g0, perrow, tid);
    stage_chunk(xb, buf1, CHUNK, CHUNK, g0, perrow, tid);

    // ---- load & scale the 12 parameters (overlaps with async loads) ----
    const int gp = active ? g : 0;
    const float* pp = params + (size_t)gp * 14;
    float raw[12];
#pragma unroll
    for (int i = 0; i < 12; i++) raw[i] = pp[i];

    const float BETA  = 1.0f   + raw[0]  * 5.0f;
    const float FC    = 50.0f  + raw[1]  * 950.0f;
    const float K0    = 0.05f  + raw[2]  * 0.85f;
    const float K1    = 0.01f  + raw[3]  * 0.49f;
    const float K2    = 0.001f + raw[4]  * 0.199f;
    const float LP    = 0.2f   + raw[5]  * 0.8f;
    const float PERCp =          raw[6]  * 10.0f;
    const float UZL   =          raw[7]  * 100.0f;
    const float TT    = -2.5f  + raw[8]  * 5.0f;
    const float CFMAX = 0.5f   + raw[9]  * 9.5f;
    const float CFR   =          raw[10] * 0.1f;
    const float CWH   =          raw[11] * 0.2f;

    const float CFRC    = CFR * CFMAX;
    const float invFC   = 1.0f / FC;
    const float invLPFC = 1.0f / (LP * FC);

    // ---- state ----
    float SNOWPACK = 1e-3f, MELTWATER = 1e-3f, SM = 1e-3f, SUZ = 1e-3f, SLZ = 1e-3f;

    float* op = out + g;

#pragma unroll 1
    for (int k = 0; k < NCH; k++) {
        // complete chunk k's loads (chunk k+1 may stay in flight)
        asm volatile("cp.async.wait_group 1;\n" ::: "memory");
        __syncthreads();

        const float* sb = (const float*)((k & 1) ? buf1 : buf0) + tid * 3;
        const int t0 = k * CHUNK;
        const int ns = min(CHUNK, NSTEP - t0);

        if (active) {
#pragma unroll 4
            for (int s = 0; s < ns; s++) {
                const float P = sb[s * (BLK * 3) + 0];
                const float T = sb[s * (BLK * 3) + 1];
                const float E = sb[s * (BLK * 3) + 2];

                // ---- snow routine ----
                const bool  rain = (T >= TT);
                const float RAIN = rain ? P : 0.0f;
                const float SNOW = rain ? 0.0f : P;
                SNOWPACK += SNOW;

                const float melt = fminf(fmaxf(CFMAX * (T - TT), 0.0f), SNOWPACK);
                MELTWATER += melt;
                SNOWPACK  -= melt;

                const float refr = fminf(fmaxf(CFRC * (TT - T), 0.0f), MELTWATER);
                SNOWPACK  += refr;
                MELTWATER -= refr;

                const float tosoil = fmaxf(MELTWATER - CWH * SNOWPACK, 0.0f);
                MELTWATER -= tosoil;

                // ---- soil routine ----
                const float r  = SM * invFC;                   // in (0, 1]
                const float sw = __saturatef(__powf(r, BETA));

                const float rt       = RAIN + tosoil;
                const float recharge = rt * sw;
                SM += rt - recharge;

                const float excess = fmaxf(SM - FC, 0.0f);
                SM -= excess;

                const float evapf = __saturatef(SM * invLPFC);
                const float ETact = fminf(SM, E * evapf);
                SM = fmaxf(SM - ETact, PRECS_F);

                // ---- response routine ----
                SUZ += recharge + excess;
                const float PERC = fminf(SUZ, PERCp);
                SUZ -= PERC;
                const float Q0 = K0 * fmaxf(SUZ - UZL, 0.0f);
                SUZ -= Q0;
                const float Q1 = K1 * SUZ;
                SUZ -= Q1;
                SLZ += PERC;
                const float Q2 = K2 * SLZ;
                SLZ -= Q2;

                __stcs(op + (size_t)(t0 + s) * NGRID, Q0 + Q1 + Q2);
            }
        }

        __syncthreads();   // chunk-k buffer fully consumed before re-staging it

        const int t2 = (k + 2) * CHUNK;
        if (t2 < NSTEP) {
            stage_chunk(xb, (k & 1) ? buf1 : buf0, t2,
                        min(CHUNK, NSTEP - t2), g0, perrow, tid);
        } else {
            // keep the async group count aligned for wait_group 1
            asm volatile("cp.async.commit_group;\n" ::: "memory");
        }
    }
}

extern "C" void kernel_launch(void* const* d_in, const int* in_sizes, int n_in,
                              void* d_out, int out_size)
{
    const float* x      = (const float*)d_in[0];   // (365, 50000, 3)
    const float* params = (const float*)d_in[1];   // (50000, 14)
    float* out = (float*)d_out;                    // (365, 50000, 1)

    static bool attr_set = false;
    if (!attr_set) {
        cudaFuncSetAttribute(hbv_kernel,
                             cudaFuncAttributeMaxDynamicSharedMemorySize,
                             2 * BUFB);
        attr_set = true;
    }

    const int blocks = (NGRID + BLK - 1) / BLK;    // 143
    hbv_kernel<<<blocks, BLK, 2 * BUFB>>>(x, params, out);
}

// round 10
// speedup vs baseline: 1.6300x; 1.0589x over previous
#include <cuda_runtime.h>
#include <cuda_bf16.h>
#include <cstdint>

#define NSTEP   365
#define NGRID   50000
#define PRECS_F 1e-5f
#define BLK     352                     // 11 warps; 143 blocks -> 1 block/SM, balanced
#define CHUNK   16                      // timesteps staged per smem buffer
#define ROWB    (BLK * 12)              // 4224 bytes of x per timestep per block
#define BUFB    (ROWB * CHUNK)          // 67584 bytes per buffer
#define NBUF    3                       // triple buffer: 202752 B smem
#define NCH     ((NSTEP + CHUNK - 1) / CHUNK)   // 23 chunks (22 full + 13-step tail)

extern __shared__ char smem_raw[];      // NBUF * BUFB

// Stage `nrows` timestep-rows of this block's x slice into sbuf via cp.async.
// Every thread executes the commit (uniform), so group counting stays aligned.
__device__ __forceinline__ void stage_chunk(const char* __restrict__ xbase,
                                            char* sbuf, int t0, int nrows,
                                            int g0, int perrow, int tid)
{
    if (tid < perrow) {
        const char* gsrc = xbase + (size_t)t0 * (size_t)(NGRID * 12)
                                 + (size_t)g0 * 12 + (size_t)tid * 16;
        uint32_t sdst = (uint32_t)__cvta_generic_to_shared(sbuf) + tid * 16;
#pragma unroll
        for (int r = 0; r < CHUNK; r++) {
            if (r < nrows) {
                asm volatile("cp.async.cg.shared.global [%0], [%1], 16;\n"
                             :: "r"(sdst + r * ROWB),
                                "l"(gsrc + (size_t)r * (size_t)(NGRID * 12))
                             : "memory");
            }
        }
    }
    asm volatile("cp.async.commit_group;\n" ::: "memory");
}

__global__ __launch_bounds__(BLK, 1)
void hbv_kernel(const float* __restrict__ x,
                const float* __restrict__ params,
                float* __restrict__ out)
{
    const int tid = threadIdx.x;
    const int g0  = blockIdx.x * BLK;
    const int g   = g0 + tid;
    const bool active = (g < NGRID);

    const int ncells = min(BLK, NGRID - g0);       // 352, or 16 for last block
    const int perrow = (ncells * 12) / 16;         // 16B cp.async ops per row

    // ---- kick off the first two chunk loads immediately (depth-2 prefetch) ----
    const char* xb = (const char*)x;
    stage_chunk(xb, smem_raw,        0,     CHUNK, g0, perrow, tid);
    stage_chunk(xb, smem_raw + BUFB, CHUNK, CHUNK, g0, perrow, tid);

    // ---- load & scale the 12 parameters (overlaps with async loads) ----
    const int gp = active ? g : 0;
    const float* pp = params + (size_t)gp * 14;
    float raw[12];
#pragma unroll
    for (int i = 0; i < 12; i++) raw[i] = pp[i];

    const float BETA  = 1.0f   + raw[0]  * 5.0f;
    const float FC    = 50.0f  + raw[1]  * 950.0f;
    const float K0    = 0.05f  + raw[2]  * 0.85f;
    const float K1    = 0.01f  + raw[3]  * 0.49f;
    const float K2    = 0.001f + raw[4]  * 0.199f;
    const float LP    = 0.2f   + raw[5]  * 0.8f;
    const float PERCp =          raw[6]  * 10.0f;
    const float UZL   =          raw[7]  * 100.0f;
    const float TT    = -2.5f  + raw[8]  * 5.0f;
    const float CFMAX = 0.5f   + raw[9]  * 9.5f;
    const float CFR   =          raw[10] * 0.1f;
    const float CWH   =          raw[11] * 0.2f;

    const float CFRC     = CFR * CFMAX;
    const float CFMAX_TT = CFMAX * TT;     // melt  = fma(CFMAX, T, -CFMAX_TT)
    const float CFRC_TT  = CFRC * TT;      // refr  = fma(-CFRC, T,  CFRC_TT)
    const float invFC    = 1.0f / FC;
    const float invLPFC  = 1.0f / (LP * FC);

    // ---- state ----
    float SNOWPACK = 1e-3f, MELTWATER = 1e-3f, SM = 1e-3f, SUZ = 1e-3f, SLZ = 1e-3f;

    float* o = out + g;                    // advances by NGRID each step

#pragma unroll 1
    for (int k = 0; k < NCH; k++) {
        // chunk k arrived (chunk k+1 may stay in flight)
        asm volatile("cp.async.wait_group 1;\n" ::: "memory");
        __syncthreads();   // data visible + everyone done reading buffer (k-1)%3

        char* bufk = smem_raw + (k % NBUF) * BUFB;
        const float* sb = (const float*)bufk + tid * 3;
        const int t0 = k * CHUNK;
        const int ns = min(CHUNK, NSTEP - t0);

        if (active) {
#pragma unroll 4
            for (int s = 0; s < ns; s++) {
                const float P = sb[0];
                const float T = sb[1];
                const float E = sb[2];
                sb += BLK * 3;

                // ---- snow routine ----
                const float RAIN = (T >= TT) ? P : 0.0f;
                SNOWPACK += P - RAIN;

                const float melt = fminf(fmaxf(fmaf(CFMAX, T, -CFMAX_TT), 0.0f), SNOWPACK);
                MELTWATER += melt;
                SNOWPACK  -= melt;

                const float refr = fminf(fmaxf(fmaf(-CFRC, T, CFRC_TT), 0.0f), MELTWATER);
                SNOWPACK  += refr;
                MELTWATER -= refr;

                const float tosoil = fmaxf(fmaf(-CWH, SNOWPACK, MELTWATER), 0.0f);
                MELTWATER -= tosoil;

                // ---- soil routine ----
                const float r  = SM * invFC;                   // in (0, 1]
                const float sw = __saturatef(__powf(r, BETA));

                const float rt       = RAIN + tosoil;
                const float recharge = rt * sw;
                SM += rt - recharge;

                const float excess = fmaxf(SM - FC, 0.0f);
                SM = fminf(SM, FC);                            // == SM - excess

                const float evapf = __saturatef(SM * invLPFC);
                const float ETact = fminf(SM, E * evapf);
                SM = fmaxf(SM - ETact, PRECS_F);

                // ---- response routine ----
                SUZ += recharge + excess;
                const float PERC = fminf(SUZ, PERCp);
                SUZ -= PERC;
                const float Q0 = K0 * fmaxf(SUZ - UZL, 0.0f);
                SUZ -= Q0;
                const float Q1 = K1 * SUZ;
                SUZ -= Q1;
                SLZ += PERC;
                const float Q2 = K2 * SLZ;
                SLZ -= Q2;

                __stcs(o, Q0 + Q1 + Q2);
                o += NGRID;
            }
        }

        // Stage chunk k+2 into buffer (k+2)%3 == (k-1)%3 — the buffer consumed
        // LAST iteration; every thread passed this iteration's barrier after
        // finishing it, so no second __syncthreads is needed.
        const int t2 = (k + 2) * CHUNK;
        if (t2 < NSTEP) {
            stage_chunk(xb, smem_raw + ((k + 2) % NBUF) * BUFB, t2,
                        min(CHUNK, NSTEP - t2), g0, perrow, tid);
        } else {
            // keep the async group count aligned for wait_group 1
            asm volatile("cp.async.commit_group;\n" ::: "memory");
        }
    }
}

extern "C" void kernel_launch(void* const* d_in, const int* in_sizes, int n_in,
                              void* d_out, int out_size)
{
    const float* x      = (const float*)d_in[0];   // (365, 50000, 3)
    const float* params = (const float*)d_in[1];   // (50000, 14)
    float* out = (float*)d_out;                    // (365, 50000, 1)

    static bool attr_set = false;
    if (!attr_set) {
        cudaFuncSetAttribute(hbv_kernel,
                             cudaFuncAttributeMaxDynamicSharedMemorySize,
                             NBUF * BUFB);
        attr_set = true;
    }

    const int blocks = (NGRID + BLK - 1) / BLK;    // 143
    hbv_kernel<<<blocks, BLK, NBUF * BUFB>>>(x, params, out);
}